// round 7
// baseline (speedup 1.0000x reference)
#include <cuda_runtime.h>
#include <cuda_fp16.h>

// ---------------------------------------------------------------------------
// SSIM3D: two fp32 volumes (4,1,160,160,160), 11-tap separable Gaussian,
// 5 statistics (mu1, mu2, E11, E22, E12), scalar mean output.
//
// R7:
//  - pass_xy: UNCHANGED from R6 (measured 114.75us): 32x80 tiles, x-conv +
//    y-conv, packed f32x2, fp16 mid.
//  - pass_b: z-sliding scatter (R4-validated logic), f32x2-packed x-pairs,
//    no smem / no syncs, mid read exactly once, packed SSIM + reduction.
// ---------------------------------------------------------------------------

typedef unsigned long long u64t;

namespace {
constexpr int D    = 160;
constexpr int DD   = D * D;                 // 25600
constexpr int NB   = 4;
constexpr long long VOL  = (long long)D * DD;       // 4,096,000
constexpr long long NIMG = (long long)NB * VOL;     // 16,384,000
constexpr int RXA = 42;   // pass_xy region width  (x)
constexpr int RYA = 90;   // pass_xy region height (y)
constexpr int SXA = 43;   // u64 stride, interleaved input tile
constexpr int TSA = 33;   // stride of x-conv planes
constexpr float C1 = 0.0001f;
constexpr float C2 = 0.0009f;
// pass_xy dynamic smem layout (u64 units)
constexpr int OFF_TM = RYA * SXA;            // 3870
constexpr int OFF_TE = OFF_TM + RYA * TSA;   // 6840
constexpr int OFF_TS = OFF_TE + RYA * TSA;   // 9810
constexpr int SMEM_XY = (OFF_TS + (RYA * TSA + 1) / 2) * 8;   // 90368 B
}

__device__ constexpr float W[11] = {
    0.00102838f, 0.00759876f, 0.03600077f, 0.10936070f, 0.21300554f,
    0.26601173f,
    0.21300554f, 0.10936070f, 0.03600077f, 0.00759876f, 0.00102838f};

// 5 channels x 4 batches x 160^3 halfs = 163.84 MB scratch.
__device__ __half g_mid[5ll * 16384000ll];
__device__ double g_sum;

// ---- packed f32x2 helpers ----
__device__ __forceinline__ u64t pk(float x, float y) {
    u64t r; asm("mov.b64 %0, {%1, %2};" : "=l"(r) : "f"(x), "f"(y)); return r;
}
__device__ __forceinline__ float2 unpk(u64t v) {
    float2 f; asm("mov.b64 {%0, %1}, %2;" : "=f"(f.x), "=f"(f.y) : "l"(v));
    return f;
}
__device__ __forceinline__ u64t fma2(u64t a, u64t w, u64t d) {
    asm("fma.rn.f32x2 %0, %1, %2, %0;" : "+l"(d) : "l"(a), "l"(w));
    return d;
}
__device__ __forceinline__ u64t mul2(u64t a, u64t b) {
    u64t r; asm("mul.rn.f32x2 %0, %1, %2;" : "=l"(r) : "l"(a), "l"(b));
    return r;
}
__device__ __forceinline__ u64t add2(u64t a, u64t b) {
    u64t r; asm("add.rn.f32x2 %0, %1, %2;" : "=l"(r) : "l"(a), "l"(b));
    return r;
}
__device__ __forceinline__ u64t neg2(u64t a) {
    return a ^ 0x8000000080000000ull;
}
// Packed reciprocal: bit-trick seed (no cross-lane borrow: both halves of
// den are positive with bits < 0x7EF311C3) + 3 Newton steps. FMA-pipe only.
__device__ __forceinline__ u64t rcp2(u64t x, u64t two2) {
    u64t r = 0x7EF311C37EF311C3ull - x;
#pragma unroll
    for (int it = 0; it < 3; it++)
        r = mul2(r, add2(two2, neg2(mul2(x, r))));
    return r;
}

// ---------------------------------------------------------------------------
// Pass A: x-conv then y-conv for one 32(x) x 80(y) tile of one z-slice.
// grid = (10 tiles, 160 z, 4 b), block = 576 threads.  (unchanged from R6)
// ---------------------------------------------------------------------------
__global__ void __launch_bounds__(576, 1)
pass_xy(const float* __restrict__ img1, const float* __restrict__ img2) {
    extern __shared__ u64t dsm[];
    u64t* sAC = dsm;                 // (a,c) interleaved input, [90][43]
    u64t* tm  = dsm + OFF_TM;        // (m1,m2)   x-conv plane, [90][33]
    u64t* te  = dsm + OFF_TE;        // (e11,e22) x-conv plane, [90][33]
    float* ts = (float*)(dsm + OFF_TS);   // e12 x-conv plane, [90][33]

    const int tile = blockIdx.x;            // 0..9
    const int x0 = (tile % 5) * 32;
    const int y0 = (tile / 5) * 80;
    const int z  = blockIdx.y;
    const int b  = blockIdx.z;
    const int tid = threadIdx.x;

    if (tile == 0 && z == 0 && b == 0 && tid == 0) g_sum = 0.0;  // fold init

    const float* p1 = img1 + (long long)b * VOL + (long long)z * DD;
    const float* p2 = img2 + (long long)b * VOL + (long long)z * DD;

    // Stage 1: prefetch 42x90 halo region (MLP-batched), store interleaved.
    {
        float ra[7], rc[7];
#pragma unroll
        for (int it = 0; it < 7; it++) {
            const int l = tid + it * 576;
            float a = 0.f, c = 0.f;
            if (l < RYA * RXA) {
                const int j = l / RXA, i = l - j * RXA;
                const int gy = y0 - 5 + j;
                const int gx = x0 - 5 + i;
                if (gy >= 0 && gy < D && gx >= 0 && gx < D) {
                    a = p1[gy * D + gx];
                    c = p2[gy * D + gx];
                }
            }
            ra[it] = a; rc[it] = c;
        }
#pragma unroll
        for (int it = 0; it < 7; it++) {
            const int l = tid + it * 576;
            if (l < RYA * RXA)
                sAC[(l / RXA) * SXA + (l % RXA)] = pk(ra[it], rc[it]);
        }
    }
    __syncthreads();

    u64t W2[11];
#pragma unroll
    for (int k = 0; k < 11; k++) W2[k] = pk(W[k], W[k]);

    // Stage 2: x-conv, 90 rows x 8 chunks of 4 outputs = 720 units.
    for (int u = tid; u < RYA * 8; u += 576) {
        const int row   = u % RYA;
        const int chunk = u / RYA;
        const int base = row * SXA + chunk * 4;
        u64t ac[14], sq[14];
        float p12[14];
#pragma unroll
        for (int j = 0; j < 14; j++) ac[j] = sAC[base + j];
#pragma unroll
        for (int j = 0; j < 14; j++) {
            sq[j] = mul2(ac[j], ac[j]);
            const float2 t = unpk(ac[j]);
            p12[j] = t.x * t.y;
        }
#pragma unroll
        for (int i = 0; i < 4; i++) {
            u64t am = 0ull, ae = 0ull;
            float a12 = 0.f;
#pragma unroll
            for (int k = 0; k < 11; k++) {
                am  = fma2(ac[i + k], W2[k], am);
                ae  = fma2(sq[i + k], W2[k], ae);
                a12 = fmaf(W[k], p12[i + k], a12);
            }
            const int x = chunk * 4 + i;
            tm[row * TSA + x] = am;
            te[row * TSA + x] = ae;
            ts[row * TSA + x] = a12;
        }
    }
    __syncthreads();

    // Stage 3: y-conv (80 outputs in 8 chunks of 10), write fp16 planes.
    const long long cs = (long long)NB * VOL;
    for (int u = tid; u < 768; u += 576) {
        const int g = u >> 8;
        const int r = u & 255;
        const int tx = r & 31;
        const int sub = r >> 5;              // y chunk of 10
        __half* o0 = g_mid + (long long)b * VOL + (long long)z * DD + x0 + tx;

        if (g < 2) {
            const u64t* tp = (g == 0) ? tm : te;
            __half* q0 = o0 + (g == 0 ? 0 : 2 * cs);
            __half* q1 = q0 + cs;
            u64t v[20];
#pragma unroll
            for (int j = 0; j < 20; j++)
                v[j] = tp[(sub * 10 + j) * TSA + tx];
#pragma unroll
            for (int i = 0; i < 10; i++) {
                u64t acc = 0ull;
#pragma unroll
                for (int k = 0; k < 11; k++) acc = fma2(v[i + k], W2[k], acc);
                const float2 f = unpk(acc);
                const long long yo = (long long)(y0 + sub * 10 + i) * D;
                q0[yo] = __float2half_rn(f.x);
                q1[yo] = __float2half_rn(f.y);
            }
        } else {
            __half* q4 = o0 + 4 * cs;
            float v[20];
#pragma unroll
            for (int j = 0; j < 20; j++)
                v[j] = ts[(sub * 10 + j) * TSA + tx];
#pragma unroll
            for (int i = 0; i < 10; i++) {
                float acc = 0.f;
#pragma unroll
                for (int k = 0; k < 11; k++) acc = fmaf(W[k], v[i + k], acc);
                q4[(long long)(y0 + sub * 10 + i) * D] = __float2half_rn(acc);
            }
        }
    }
}

// ---------------------------------------------------------------------------
// Pass B: z-sliding scatter + packed SSIM + reduction. No smem tiles, no
// syncs in the mainloop; the fp16 mid is streamed exactly once.
// grid = (160 y, 4 b), block = 96 threads (80 active x-pairs).
// ---------------------------------------------------------------------------
__global__ void __launch_bounds__(96) pass_b() {
    __shared__ float red[3];

    const int y = blockIdx.x;
    const int b = blockIdx.y;
    const int tid = threadIdx.x;
    const bool act = tid < 80;
    const int xp = act ? tid : 0;          // x-pair index 0..79

    const long long cs = (long long)NB * VOL;
    const __half* base = g_mid + (long long)b * VOL + (long long)y * D + 2 * xp;

    u64t W2[11];
#pragma unroll
    for (int k = 0; k < 11; k++) W2[k] = pk(W[k], W[k]);
    const u64t two2 = pk(2.f, 2.f);
    const u64t c1p  = pk(C1, C1);
    const u64t c2p  = pk(C2, C2);

    u64t A[5][11];
#pragma unroll
    for (int ch = 0; ch < 5; ch++)
#pragma unroll
        for (int s = 0; s < 11; s++) A[ch][s] = 0ull;

    u64t lacc = 0ull;

    // ---- Prologue: z = 0..4 (guard out-of-range outputs) ----
#pragma unroll
    for (int z = 0; z < 5; z++) {
        u64t v[5];
#pragma unroll
        for (int ch = 0; ch < 5; ch++) {
            v[ch] = 0ull;
            if (act) {
                const __half2 h =
                    *(const __half2*)(base + ch * cs + (long long)z * DD);
                const float2 f = __half22float2(h);
                v[ch] = pk(f.x, f.y);
            }
        }
#pragma unroll
        for (int d = 0; d < 11; d++) {
            if (d >= 5 - z) {
                const int sl = (z - 5 + d + 11) % 11;   // compile-time
#pragma unroll
                for (int ch = 0; ch < 5; ch++)
                    A[ch][sl] = fma2(v[ch], W2[10 - d], A[ch][sl]);
            }
        }
    }

    // ---- Steady state: z = 5..169, emit output o = z-5 ----
    for (int zb = 0; zb < 165; zb += 11) {
#pragma unroll
        for (int s = 0; s < 11; s++) {
            const int z = 5 + zb + s;

            u64t v[5];
#pragma unroll
            for (int ch = 0; ch < 5; ch++) {
                v[ch] = 0ull;
                if (act && z < D) {
                    const __half2 h =
                        *(const __half2*)(base + ch * cs + (long long)z * DD);
                    const float2 f = __half22float2(h);
                    v[ch] = pk(f.x, f.y);
                }
            }

#pragma unroll
            for (int d = 0; d < 11; d++) {
                const int sl = (s + d) % 11;            // compile-time
#pragma unroll
                for (int ch = 0; ch < 5; ch++)
                    A[ch][sl] = fma2(v[ch], W2[10 - d], A[ch][sl]);
            }

            const int o = zb + s;
            if (o < D) {
                const u64t mu1 = A[0][s], mu2 = A[1][s];
                const u64t e11 = A[2][s], e22 = A[3][s], e12 = A[4][s];
                const u64t mu1s = mul2(mu1, mu1);
                const u64t mu2s = mul2(mu2, mu2);
                const u64t mu12 = mul2(mu1, mu2);
                const u64t num1 = fma2(mu12, two2, c1p);
                const u64t num2 = fma2(add2(e12, neg2(mu12)), two2, c2p);
                const u64t den1 = add2(add2(mu1s, mu2s), c1p);
                const u64t den2 = add2(add2(add2(e11, neg2(mu1s)),
                                            add2(e22, neg2(mu2s))), c2p);
                lacc = fma2(mul2(num1, num2), rcp2(mul2(den1, den2), two2),
                            lacc);
            }
#pragma unroll
            for (int ch = 0; ch < 5; ch++) A[ch][s] = 0ull;
        }
    }

    const float2 lf = unpk(lacc);
    float lsum = act ? (lf.x + lf.y) : 0.f;

    // Block reduction (3 warps).
#pragma unroll
    for (int o = 16; o > 0; o >>= 1)
        lsum += __shfl_xor_sync(0xffffffffu, lsum, o);
    if ((tid & 31) == 0) red[tid >> 5] = lsum;
    __syncthreads();
    if (tid == 0)
        atomicAdd(&g_sum, (double)(red[0] + red[1] + red[2]));
}

__global__ void fin_kernel(float* __restrict__ out) {
    out[0] = (float)(g_sum / (double)NIMG);
}

extern "C" void kernel_launch(void* const* d_in, const int* in_sizes, int n_in,
                              void* d_out, int out_size) {
    const float* img1 = (const float*)d_in[0];
    const float* img2 = (const float*)d_in[1];
    (void)in_sizes; (void)n_in; (void)out_size;

    cudaFuncSetAttribute(pass_xy, cudaFuncAttributeMaxDynamicSharedMemorySize,
                         SMEM_XY);

    dim3 grid(10, 160, 4);
    pass_xy<<<grid, 576, SMEM_XY>>>(img1, img2);
    dim3 gridb(160, 4);
    pass_b<<<gridb, 96>>>();
    fin_kernel<<<1, 1>>>((float*)d_out);
}

// round 8
// speedup vs baseline: 1.6848x; 1.6848x over previous
#include <cuda_runtime.h>
#include <cuda_fp16.h>

// ---------------------------------------------------------------------------
// SSIM3D: two fp32 volumes (4,1,160,160,160), 11-tap separable Gaussian,
// 5 statistics (mu1, mu2, E11, E22, E12), scalar mean output.
//
// R8:
//  - pass_xy: UNCHANGED (measured ~115us): 32x80 tiles, x-conv + y-conv,
//    packed f32x2, fp16 mid.
//  - pass_z: back to the R5-measured configuration: 32(x) x 32(z) tiles,
//    128 threads, 28.5 kB smem (high occupancy), f32x2 z-conv + packed SSIM.
// ---------------------------------------------------------------------------

typedef unsigned long long u64t;

namespace {
constexpr int D    = 160;
constexpr int DD   = D * D;                 // 25600
constexpr int NB   = 4;
constexpr long long VOL  = (long long)D * DD;       // 4,096,000
constexpr long long NIMG = (long long)NB * VOL;     // 16,384,000
constexpr int RXA = 42;   // pass_xy region width  (x)
constexpr int RYA = 90;   // pass_xy region height (y)
constexpr int SXA = 43;   // u64 stride, interleaved input tile
constexpr int TSA = 33;   // stride of x-conv planes
constexpr int RZ  = 42;   // pass_z region (z)
constexpr int UZP = 17;   // u64 stride, pass_z tile (x-pairs)
constexpr float C1 = 0.0001f;
constexpr float C2 = 0.0009f;
// pass_xy dynamic smem layout (u64 units)
constexpr int OFF_TM = RYA * SXA;            // 3870
constexpr int OFF_TE = OFF_TM + RYA * TSA;   // 6840
constexpr int OFF_TS = OFF_TE + RYA * TSA;   // 9810
constexpr int SMEM_XY = (OFF_TS + (RYA * TSA + 1) / 2) * 8;   // 90368 B
}

__device__ constexpr float W[11] = {
    0.00102838f, 0.00759876f, 0.03600077f, 0.10936070f, 0.21300554f,
    0.26601173f,
    0.21300554f, 0.10936070f, 0.03600077f, 0.00759876f, 0.00102838f};

// 5 channels x 4 batches x 160^3 halfs = 163.84 MB scratch.
__device__ __half g_mid[5ll * 16384000ll];
__device__ double g_sum;

// ---- packed f32x2 helpers ----
__device__ __forceinline__ u64t pk(float x, float y) {
    u64t r; asm("mov.b64 %0, {%1, %2};" : "=l"(r) : "f"(x), "f"(y)); return r;
}
__device__ __forceinline__ float2 unpk(u64t v) {
    float2 f; asm("mov.b64 {%0, %1}, %2;" : "=f"(f.x), "=f"(f.y) : "l"(v));
    return f;
}
__device__ __forceinline__ u64t fma2(u64t a, u64t w, u64t d) {
    asm("fma.rn.f32x2 %0, %1, %2, %0;" : "+l"(d) : "l"(a), "l"(w));
    return d;
}
__device__ __forceinline__ u64t mul2(u64t a, u64t b) {
    u64t r; asm("mul.rn.f32x2 %0, %1, %2;" : "=l"(r) : "l"(a), "l"(b));
    return r;
}
__device__ __forceinline__ u64t add2(u64t a, u64t b) {
    u64t r; asm("add.rn.f32x2 %0, %1, %2;" : "=l"(r) : "l"(a), "l"(b));
    return r;
}
__device__ __forceinline__ u64t neg2(u64t a) {
    return a ^ 0x8000000080000000ull;
}
// Packed reciprocal: bit-trick seed (no cross-lane borrow: both halves of
// den are positive with bits < 0x7EF311C3) + 3 Newton steps. FMA-pipe only.
__device__ __forceinline__ u64t rcp2(u64t x, u64t two2) {
    u64t r = 0x7EF311C37EF311C3ull - x;
#pragma unroll
    for (int it = 0; it < 3; it++)
        r = mul2(r, add2(two2, neg2(mul2(x, r))));
    return r;
}

// ---------------------------------------------------------------------------
// Pass A: x-conv then y-conv for one 32(x) x 80(y) tile of one z-slice.
// grid = (10 tiles, 160 z, 4 b), block = 576 threads.  (unchanged)
// ---------------------------------------------------------------------------
__global__ void __launch_bounds__(576, 1)
pass_xy(const float* __restrict__ img1, const float* __restrict__ img2) {
    extern __shared__ u64t dsm[];
    u64t* sAC = dsm;                 // (a,c) interleaved input, [90][43]
    u64t* tm  = dsm + OFF_TM;        // (m1,m2)   x-conv plane, [90][33]
    u64t* te  = dsm + OFF_TE;        // (e11,e22) x-conv plane, [90][33]
    float* ts = (float*)(dsm + OFF_TS);   // e12 x-conv plane, [90][33]

    const int tile = blockIdx.x;            // 0..9
    const int x0 = (tile % 5) * 32;
    const int y0 = (tile / 5) * 80;
    const int z  = blockIdx.y;
    const int b  = blockIdx.z;
    const int tid = threadIdx.x;

    if (tile == 0 && z == 0 && b == 0 && tid == 0) g_sum = 0.0;  // fold init

    const float* p1 = img1 + (long long)b * VOL + (long long)z * DD;
    const float* p2 = img2 + (long long)b * VOL + (long long)z * DD;

    // Stage 1: prefetch 42x90 halo region (MLP-batched), store interleaved.
    {
        float ra[7], rc[7];
#pragma unroll
        for (int it = 0; it < 7; it++) {
            const int l = tid + it * 576;
            float a = 0.f, c = 0.f;
            if (l < RYA * RXA) {
                const int j = l / RXA, i = l - j * RXA;
                const int gy = y0 - 5 + j;
                const int gx = x0 - 5 + i;
                if (gy >= 0 && gy < D && gx >= 0 && gx < D) {
                    a = p1[gy * D + gx];
                    c = p2[gy * D + gx];
                }
            }
            ra[it] = a; rc[it] = c;
        }
#pragma unroll
        for (int it = 0; it < 7; it++) {
            const int l = tid + it * 576;
            if (l < RYA * RXA)
                sAC[(l / RXA) * SXA + (l % RXA)] = pk(ra[it], rc[it]);
        }
    }
    __syncthreads();

    u64t W2[11];
#pragma unroll
    for (int k = 0; k < 11; k++) W2[k] = pk(W[k], W[k]);

    // Stage 2: x-conv, 90 rows x 8 chunks of 4 outputs = 720 units.
    for (int u = tid; u < RYA * 8; u += 576) {
        const int row   = u % RYA;
        const int chunk = u / RYA;
        const int base = row * SXA + chunk * 4;
        u64t ac[14], sq[14];
        float p12[14];
#pragma unroll
        for (int j = 0; j < 14; j++) ac[j] = sAC[base + j];
#pragma unroll
        for (int j = 0; j < 14; j++) {
            sq[j] = mul2(ac[j], ac[j]);
            const float2 t = unpk(ac[j]);
            p12[j] = t.x * t.y;
        }
#pragma unroll
        for (int i = 0; i < 4; i++) {
            u64t am = 0ull, ae = 0ull;
            float a12 = 0.f;
#pragma unroll
            for (int k = 0; k < 11; k++) {
                am  = fma2(ac[i + k], W2[k], am);
                ae  = fma2(sq[i + k], W2[k], ae);
                a12 = fmaf(W[k], p12[i + k], a12);
            }
            const int x = chunk * 4 + i;
            tm[row * TSA + x] = am;
            te[row * TSA + x] = ae;
            ts[row * TSA + x] = a12;
        }
    }
    __syncthreads();

    // Stage 3: y-conv (80 outputs in 8 chunks of 10), write fp16 planes.
    const long long cs = (long long)NB * VOL;
    for (int u = tid; u < 768; u += 576) {
        const int g = u >> 8;
        const int r = u & 255;
        const int tx = r & 31;
        const int sub = r >> 5;              // y chunk of 10
        __half* o0 = g_mid + (long long)b * VOL + (long long)z * DD + x0 + tx;

        if (g < 2) {
            const u64t* tp = (g == 0) ? tm : te;
            __half* q0 = o0 + (g == 0 ? 0 : 2 * cs);
            __half* q1 = q0 + cs;
            u64t v[20];
#pragma unroll
            for (int j = 0; j < 20; j++)
                v[j] = tp[(sub * 10 + j) * TSA + tx];
#pragma unroll
            for (int i = 0; i < 10; i++) {
                u64t acc = 0ull;
#pragma unroll
                for (int k = 0; k < 11; k++) acc = fma2(v[i + k], W2[k], acc);
                const float2 f = unpk(acc);
                const long long yo = (long long)(y0 + sub * 10 + i) * D;
                q0[yo] = __float2half_rn(f.x);
                q1[yo] = __float2half_rn(f.y);
            }
        } else {
            __half* q4 = o0 + 4 * cs;
            float v[20];
#pragma unroll
            for (int j = 0; j < 20; j++)
                v[j] = ts[(sub * 10 + j) * TSA + tx];
#pragma unroll
            for (int i = 0; i < 10; i++) {
                float acc = 0.f;
#pragma unroll
                for (int k = 0; k < 11; k++) acc = fmaf(W[k], v[i + k], acc);
                q4[(long long)(y0 + sub * 10 + i) * D] = __float2half_rn(acc);
            }
        }
    }
}

// ---------------------------------------------------------------------------
// Pass B: z-conv + packed SSIM + reduction, 32(x) x 32(z) tiles (R5 config).
// grid = (25 tiles [x,z], 160 y, 4 b), block = 128 threads.
// ---------------------------------------------------------------------------
__global__ void __launch_bounds__(128) pass_z() {
    __shared__ u64t u5[5 * RZ * UZP];   // 28.56 kB
    __shared__ float red[4];

    const int tile = blockIdx.x;
    const int x0 = (tile % 5) * 32;
    const int z0 = (tile / 5) * 32;
    const int y  = blockIdx.y;
    const int b  = blockIdx.z;
    const int tid = threadIdx.x;

    const long long cs = (long long)NB * VOL;
    const __half* basep = g_mid + (long long)b * VOL + (long long)y * D + x0;

    // Fill: 5 channels x 42 z-rows x 16 x-pairs (zero pad in z).
    for (int l = tid; l < 5 * RZ * 16; l += 128) {
        const int ch = l / (RZ * 16);
        const int rem = l - ch * (RZ * 16);
        const int zz = rem >> 4;
        const int p  = rem & 15;
        const int gz = z0 - 5 + zz;
        float2 v = make_float2(0.f, 0.f);
        if (gz >= 0 && gz < D) {
            const __half2 h =
                *(const __half2*)(basep + ch * cs + (long long)gz * DD + 2 * p);
            v = __half22float2(h);
        }
        u5[(ch * RZ + zz) * UZP + p] = pk(v.x, v.y);
    }
    __syncthreads();

    u64t W2[11];
#pragma unroll
    for (int k = 0; k < 11; k++) W2[k] = pk(W[k], W[k]);

    // Each thread: one x-pair, 4 z-outputs.
    const int xp = tid & 15;
    const int zc = tid >> 4;            // 0..7
    u64t rr[5][4];
#pragma unroll
    for (int ch = 0; ch < 5; ch++) {
        u64t v[14];
#pragma unroll
        for (int j = 0; j < 14; j++)
            v[j] = u5[(ch * RZ + zc * 4 + j) * UZP + xp];
#pragma unroll
        for (int i = 0; i < 4; i++) {
            u64t acc = 0ull;
#pragma unroll
            for (int k = 0; k < 11; k++) acc = fma2(v[i + k], W2[k], acc);
            rr[ch][i] = acc;
        }
    }

    // Packed SSIM map.
    const u64t two2 = pk(2.f, 2.f);
    const u64t c1p  = pk(C1, C1);
    const u64t c2p  = pk(C2, C2);
    u64t lacc = 0ull;
#pragma unroll
    for (int i = 0; i < 4; i++) {
        const u64t mu1 = rr[0][i], mu2 = rr[1][i];
        const u64t e11 = rr[2][i], e22 = rr[3][i], e12 = rr[4][i];
        const u64t mu1s = mul2(mu1, mu1);
        const u64t mu2s = mul2(mu2, mu2);
        const u64t mu12 = mul2(mu1, mu2);
        const u64t num1 = fma2(mu12, two2, c1p);
        const u64t num2 = fma2(add2(e12, neg2(mu12)), two2, c2p);
        const u64t den1 = add2(add2(mu1s, mu2s), c1p);
        const u64t den2 = add2(add2(add2(e11, neg2(mu1s)),
                                    add2(e22, neg2(mu2s))), c2p);
        lacc = fma2(mul2(num1, num2), rcp2(mul2(den1, den2), two2), lacc);
    }
    const float2 lf = unpk(lacc);
    float lsum = lf.x + lf.y;

    // Block reduction (4 warps).
#pragma unroll
    for (int o = 16; o > 0; o >>= 1)
        lsum += __shfl_xor_sync(0xffffffffu, lsum, o);
    if ((tid & 31) == 0) red[tid >> 5] = lsum;
    __syncthreads();
    if (tid == 0) {
        float s = 0.f;
#pragma unroll
        for (int w = 0; w < 4; w++) s += red[w];
        atomicAdd(&g_sum, (double)s);
    }
}

__global__ void fin_kernel(float* __restrict__ out) {
    out[0] = (float)(g_sum / (double)NIMG);
}

extern "C" void kernel_launch(void* const* d_in, const int* in_sizes, int n_in,
                              void* d_out, int out_size) {
    const float* img1 = (const float*)d_in[0];
    const float* img2 = (const float*)d_in[1];
    (void)in_sizes; (void)n_in; (void)out_size;

    cudaFuncSetAttribute(pass_xy, cudaFuncAttributeMaxDynamicSharedMemorySize,
                         SMEM_XY);

    dim3 grid(10, 160, 4);
    pass_xy<<<grid, 576, SMEM_XY>>>(img1, img2);
    dim3 gridz(25, 160, 4);
    pass_z<<<gridz, 128>>>();
    fin_kernel<<<1, 1>>>((float*)d_out);
}

// round 9
// speedup vs baseline: 1.8326x; 1.0877x over previous
#include <cuda_runtime.h>
#include <cuda_fp16.h>

// ---------------------------------------------------------------------------
// SSIM3D: two fp32 volumes (4,1,160,160,160), 11-tap separable Gaussian,
// 5 statistics (mu1, mu2, E11, E22, E12), scalar mean output.
//
// R9 = R8 with one change: pass_z's fill loop loads the fp16 mid with
// uint4 (16B) instead of half2 (4B). pass_z was MLP-capped at ~2.2 TB/s by
// 4-byte loads; 16-byte loads raise the outstanding-bytes ceiling 4x.
// ---------------------------------------------------------------------------

typedef unsigned long long u64t;

namespace {
constexpr int D    = 160;
constexpr int DD   = D * D;                 // 25600
constexpr int NB   = 4;
constexpr long long VOL  = (long long)D * DD;       // 4,096,000
constexpr long long NIMG = (long long)NB * VOL;     // 16,384,000
constexpr int RXA = 42;   // pass_xy region width  (x)
constexpr int RYA = 90;   // pass_xy region height (y)
constexpr int SXA = 43;   // u64 stride, interleaved input tile
constexpr int TSA = 33;   // stride of x-conv planes
constexpr int RZ  = 42;   // pass_z region (z)
constexpr int UZP = 17;   // u64 stride, pass_z tile (x-pairs)
constexpr float C1 = 0.0001f;
constexpr float C2 = 0.0009f;
// pass_xy dynamic smem layout (u64 units)
constexpr int OFF_TM = RYA * SXA;            // 3870
constexpr int OFF_TE = OFF_TM + RYA * TSA;   // 6840
constexpr int OFF_TS = OFF_TE + RYA * TSA;   // 9810
constexpr int SMEM_XY = (OFF_TS + (RYA * TSA + 1) / 2) * 8;   // 90368 B
}

__device__ constexpr float W[11] = {
    0.00102838f, 0.00759876f, 0.03600077f, 0.10936070f, 0.21300554f,
    0.26601173f,
    0.21300554f, 0.10936070f, 0.03600077f, 0.00759876f, 0.00102838f};

// 5 channels x 4 batches x 160^3 halfs = 163.84 MB scratch.
__device__ __half g_mid[5ll * 16384000ll];
__device__ double g_sum;

// ---- packed f32x2 helpers ----
__device__ __forceinline__ u64t pk(float x, float y) {
    u64t r; asm("mov.b64 %0, {%1, %2};" : "=l"(r) : "f"(x), "f"(y)); return r;
}
__device__ __forceinline__ float2 unpk(u64t v) {
    float2 f; asm("mov.b64 {%0, %1}, %2;" : "=f"(f.x), "=f"(f.y) : "l"(v));
    return f;
}
__device__ __forceinline__ u64t fma2(u64t a, u64t w, u64t d) {
    asm("fma.rn.f32x2 %0, %1, %2, %0;" : "+l"(d) : "l"(a), "l"(w));
    return d;
}
__device__ __forceinline__ u64t mul2(u64t a, u64t b) {
    u64t r; asm("mul.rn.f32x2 %0, %1, %2;" : "=l"(r) : "l"(a), "l"(b));
    return r;
}
__device__ __forceinline__ u64t add2(u64t a, u64t b) {
    u64t r; asm("add.rn.f32x2 %0, %1, %2;" : "=l"(r) : "l"(a), "l"(b));
    return r;
}
__device__ __forceinline__ u64t neg2(u64t a) {
    return a ^ 0x8000000080000000ull;
}
// Packed reciprocal: bit-trick seed (no cross-lane borrow: both halves of
// den are positive with bits < 0x7EF311C3) + 3 Newton steps. FMA-pipe only.
__device__ __forceinline__ u64t rcp2(u64t x, u64t two2) {
    u64t r = 0x7EF311C37EF311C3ull - x;
#pragma unroll
    for (int it = 0; it < 3; it++)
        r = mul2(r, add2(two2, neg2(mul2(x, r))));
    return r;
}

// ---------------------------------------------------------------------------
// Pass A: x-conv then y-conv for one 32(x) x 80(y) tile of one z-slice.
// grid = (10 tiles, 160 z, 4 b), block = 576 threads.  (unchanged)
// ---------------------------------------------------------------------------
__global__ void __launch_bounds__(576, 1)
pass_xy(const float* __restrict__ img1, const float* __restrict__ img2) {
    extern __shared__ u64t dsm[];
    u64t* sAC = dsm;                 // (a,c) interleaved input, [90][43]
    u64t* tm  = dsm + OFF_TM;        // (m1,m2)   x-conv plane, [90][33]
    u64t* te  = dsm + OFF_TE;        // (e11,e22) x-conv plane, [90][33]
    float* ts = (float*)(dsm + OFF_TS);   // e12 x-conv plane, [90][33]

    const int tile = blockIdx.x;            // 0..9
    const int x0 = (tile % 5) * 32;
    const int y0 = (tile / 5) * 80;
    const int z  = blockIdx.y;
    const int b  = blockIdx.z;
    const int tid = threadIdx.x;

    if (tile == 0 && z == 0 && b == 0 && tid == 0) g_sum = 0.0;  // fold init

    const float* p1 = img1 + (long long)b * VOL + (long long)z * DD;
    const float* p2 = img2 + (long long)b * VOL + (long long)z * DD;

    // Stage 1: prefetch 42x90 halo region (MLP-batched), store interleaved.
    {
        float ra[7], rc[7];
#pragma unroll
        for (int it = 0; it < 7; it++) {
            const int l = tid + it * 576;
            float a = 0.f, c = 0.f;
            if (l < RYA * RXA) {
                const int j = l / RXA, i = l - j * RXA;
                const int gy = y0 - 5 + j;
                const int gx = x0 - 5 + i;
                if (gy >= 0 && gy < D && gx >= 0 && gx < D) {
                    a = p1[gy * D + gx];
                    c = p2[gy * D + gx];
                }
            }
            ra[it] = a; rc[it] = c;
        }
#pragma unroll
        for (int it = 0; it < 7; it++) {
            const int l = tid + it * 576;
            if (l < RYA * RXA)
                sAC[(l / RXA) * SXA + (l % RXA)] = pk(ra[it], rc[it]);
        }
    }
    __syncthreads();

    u64t W2[11];
#pragma unroll
    for (int k = 0; k < 11; k++) W2[k] = pk(W[k], W[k]);

    // Stage 2: x-conv, 90 rows x 8 chunks of 4 outputs = 720 units.
    for (int u = tid; u < RYA * 8; u += 576) {
        const int row   = u % RYA;
        const int chunk = u / RYA;
        const int base = row * SXA + chunk * 4;
        u64t ac[14], sq[14];
        float p12[14];
#pragma unroll
        for (int j = 0; j < 14; j++) ac[j] = sAC[base + j];
#pragma unroll
        for (int j = 0; j < 14; j++) {
            sq[j] = mul2(ac[j], ac[j]);
            const float2 t = unpk(ac[j]);
            p12[j] = t.x * t.y;
        }
#pragma unroll
        for (int i = 0; i < 4; i++) {
            u64t am = 0ull, ae = 0ull;
            float a12 = 0.f;
#pragma unroll
            for (int k = 0; k < 11; k++) {
                am  = fma2(ac[i + k], W2[k], am);
                ae  = fma2(sq[i + k], W2[k], ae);
                a12 = fmaf(W[k], p12[i + k], a12);
            }
            const int x = chunk * 4 + i;
            tm[row * TSA + x] = am;
            te[row * TSA + x] = ae;
            ts[row * TSA + x] = a12;
        }
    }
    __syncthreads();

    // Stage 3: y-conv (80 outputs in 8 chunks of 10), write fp16 planes.
    const long long cs = (long long)NB * VOL;
    for (int u = tid; u < 768; u += 576) {
        const int g = u >> 8;
        const int r = u & 255;
        const int tx = r & 31;
        const int sub = r >> 5;              // y chunk of 10
        __half* o0 = g_mid + (long long)b * VOL + (long long)z * DD + x0 + tx;

        if (g < 2) {
            const u64t* tp = (g == 0) ? tm : te;
            __half* q0 = o0 + (g == 0 ? 0 : 2 * cs);
            __half* q1 = q0 + cs;
            u64t v[20];
#pragma unroll
            for (int j = 0; j < 20; j++)
                v[j] = tp[(sub * 10 + j) * TSA + tx];
#pragma unroll
            for (int i = 0; i < 10; i++) {
                u64t acc = 0ull;
#pragma unroll
                for (int k = 0; k < 11; k++) acc = fma2(v[i + k], W2[k], acc);
                const float2 f = unpk(acc);
                const long long yo = (long long)(y0 + sub * 10 + i) * D;
                q0[yo] = __float2half_rn(f.x);
                q1[yo] = __float2half_rn(f.y);
            }
        } else {
            __half* q4 = o0 + 4 * cs;
            float v[20];
#pragma unroll
            for (int j = 0; j < 20; j++)
                v[j] = ts[(sub * 10 + j) * TSA + tx];
#pragma unroll
            for (int i = 0; i < 10; i++) {
                float acc = 0.f;
#pragma unroll
                for (int k = 0; k < 11; k++) acc = fmaf(W[k], v[i + k], acc);
                q4[(long long)(y0 + sub * 10 + i) * D] = __float2half_rn(acc);
            }
        }
    }
}

// ---------------------------------------------------------------------------
// Pass B: z-conv + packed SSIM + reduction, 32(x) x 32(z) tiles.
// grid = (25 tiles [x,z], 160 y, 4 b), block = 128 threads.
// Fill loop uses 16-byte loads (8 halfs) for 4x the in-flight bytes.
// ---------------------------------------------------------------------------
__global__ void __launch_bounds__(128) pass_z() {
    __shared__ u64t u5[5 * RZ * UZP];   // 28.56 kB
    __shared__ float red[4];

    const int tile = blockIdx.x;
    const int x0 = (tile % 5) * 32;
    const int z0 = (tile / 5) * 32;
    const int y  = blockIdx.y;
    const int b  = blockIdx.z;
    const int tid = threadIdx.x;

    const long long cs = (long long)NB * VOL;
    const __half* basep = g_mid + (long long)b * VOL + (long long)y * D + x0;

    // Fill: 5 channels x 42 z-rows x 4 uint4-chunks (8 halfs each).
    // 840 items / 128 threads = 7 iters (batched -> high MLP).
    for (int l = tid; l < 5 * RZ * 4; l += 128) {
        const int ch  = l / (RZ * 4);
        const int rem = l - ch * (RZ * 4);
        const int zz  = rem >> 2;
        const int q   = rem & 3;
        const int gz  = z0 - 5 + zz;
        u64t w0 = 0ull, w1 = 0ull, w2 = 0ull, w3 = 0ull;
        if (gz >= 0 && gz < D) {
            const uint4 h = *(const uint4*)(basep + ch * cs +
                                            (long long)gz * DD + 8 * q);
            float2 f;
            f = __half22float2(*(const __half2*)&h.x); w0 = pk(f.x, f.y);
            f = __half22float2(*(const __half2*)&h.y); w1 = pk(f.x, f.y);
            f = __half22float2(*(const __half2*)&h.z); w2 = pk(f.x, f.y);
            f = __half22float2(*(const __half2*)&h.w); w3 = pk(f.x, f.y);
        }
        u64t* dst = &u5[(ch * RZ + zz) * UZP + 4 * q];
        dst[0] = w0; dst[1] = w1; dst[2] = w2; dst[3] = w3;
    }
    __syncthreads();

    u64t W2[11];
#pragma unroll
    for (int k = 0; k < 11; k++) W2[k] = pk(W[k], W[k]);

    // Each thread: one x-pair, 4 z-outputs.
    const int xp = tid & 15;
    const int zc = tid >> 4;            // 0..7
    u64t rr[5][4];
#pragma unroll
    for (int ch = 0; ch < 5; ch++) {
        u64t v[14];
#pragma unroll
        for (int j = 0; j < 14; j++)
            v[j] = u5[(ch * RZ + zc * 4 + j) * UZP + xp];
#pragma unroll
        for (int i = 0; i < 4; i++) {
            u64t acc = 0ull;
#pragma unroll
            for (int k = 0; k < 11; k++) acc = fma2(v[i + k], W2[k], acc);
            rr[ch][i] = acc;
        }
    }

    // Packed SSIM map.
    const u64t two2 = pk(2.f, 2.f);
    const u64t c1p  = pk(C1, C1);
    const u64t c2p  = pk(C2, C2);
    u64t lacc = 0ull;
#pragma unroll
    for (int i = 0; i < 4; i++) {
        const u64t mu1 = rr[0][i], mu2 = rr[1][i];
        const u64t e11 = rr[2][i], e22 = rr[3][i], e12 = rr[4][i];
        const u64t mu1s = mul2(mu1, mu1);
        const u64t mu2s = mul2(mu2, mu2);
        const u64t mu12 = mul2(mu1, mu2);
        const u64t num1 = fma2(mu12, two2, c1p);
        const u64t num2 = fma2(add2(e12, neg2(mu12)), two2, c2p);
        const u64t den1 = add2(add2(mu1s, mu2s), c1p);
        const u64t den2 = add2(add2(add2(e11, neg2(mu1s)),
                                    add2(e22, neg2(mu2s))), c2p);
        lacc = fma2(mul2(num1, num2), rcp2(mul2(den1, den2), two2), lacc);
    }
    const float2 lf = unpk(lacc);
    float lsum = lf.x + lf.y;

    // Block reduction (4 warps).
#pragma unroll
    for (int o = 16; o > 0; o >>= 1)
        lsum += __shfl_xor_sync(0xffffffffu, lsum, o);
    if ((tid & 31) == 0) red[tid >> 5] = lsum;
    __syncthreads();
    if (tid == 0) {
        float s = 0.f;
#pragma unroll
        for (int w = 0; w < 4; w++) s += red[w];
        atomicAdd(&g_sum, (double)s);
    }
}

__global__ void fin_kernel(float* __restrict__ out) {
    out[0] = (float)(g_sum / (double)NIMG);
}

extern "C" void kernel_launch(void* const* d_in, const int* in_sizes, int n_in,
                              void* d_out, int out_size) {
    const float* img1 = (const float*)d_in[0];
    const float* img2 = (const float*)d_in[1];
    (void)in_sizes; (void)n_in; (void)out_size;

    cudaFuncSetAttribute(pass_xy, cudaFuncAttributeMaxDynamicSharedMemorySize,
                         SMEM_XY);

    dim3 grid(10, 160, 4);
    pass_xy<<<grid, 576, SMEM_XY>>>(img1, img2);
    dim3 gridz(25, 160, 4);
    pass_z<<<gridz, 128>>>();
    fin_kernel<<<1, 1>>>((float*)d_out);
}

// round 10
// speedup vs baseline: 2.1560x; 1.1765x over previous
#include <cuda_runtime.h>
#include <cuda_fp16.h>

// ---------------------------------------------------------------------------
// SSIM3D: two fp32 volumes (4,1,160,160,160), 11-tap separable Gaussian,
// 5 statistics (mu1, mu2, E11, E22, E12), scalar mean output.
//
// R10 = R9 with pass_z occupancy work:
//  - symmetric-weight z-conv (W2: 22 -> 12 regs)
//  - __launch_bounds__(128, 4) (4 blocks/SM by RF instead of ~3)
//  - fill loop batches all 7 uint4 loads before the stores (MLP=7)
// pass_xy unchanged (measured ~115.8us, FMA-pipe bound).
// ---------------------------------------------------------------------------

typedef unsigned long long u64t;

namespace {
constexpr int D    = 160;
constexpr int DD   = D * D;                 // 25600
constexpr int NB   = 4;
constexpr long long VOL  = (long long)D * DD;       // 4,096,000
constexpr long long NIMG = (long long)NB * VOL;     // 16,384,000
constexpr int RXA = 42;   // pass_xy region width  (x)
constexpr int RYA = 90;   // pass_xy region height (y)
constexpr int SXA = 43;   // u64 stride, interleaved input tile
constexpr int TSA = 33;   // stride of x-conv planes
constexpr int RZ  = 42;   // pass_z region (z)
constexpr int UZP = 17;   // u64 stride, pass_z tile (x-pairs)
constexpr float C1 = 0.0001f;
constexpr float C2 = 0.0009f;
// pass_xy dynamic smem layout (u64 units)
constexpr int OFF_TM = RYA * SXA;            // 3870
constexpr int OFF_TE = OFF_TM + RYA * TSA;   // 6840
constexpr int OFF_TS = OFF_TE + RYA * TSA;   // 9810
constexpr int SMEM_XY = (OFF_TS + (RYA * TSA + 1) / 2) * 8;   // 90368 B
}

__device__ constexpr float W[11] = {
    0.00102838f, 0.00759876f, 0.03600077f, 0.10936070f, 0.21300554f,
    0.26601173f,
    0.21300554f, 0.10936070f, 0.03600077f, 0.00759876f, 0.00102838f};

// 5 channels x 4 batches x 160^3 halfs = 163.84 MB scratch.
__device__ __half g_mid[5ll * 16384000ll];
__device__ double g_sum;

// ---- packed f32x2 helpers ----
__device__ __forceinline__ u64t pk(float x, float y) {
    u64t r; asm("mov.b64 %0, {%1, %2};" : "=l"(r) : "f"(x), "f"(y)); return r;
}
__device__ __forceinline__ float2 unpk(u64t v) {
    float2 f; asm("mov.b64 {%0, %1}, %2;" : "=f"(f.x), "=f"(f.y) : "l"(v));
    return f;
}
__device__ __forceinline__ u64t fma2(u64t a, u64t w, u64t d) {
    asm("fma.rn.f32x2 %0, %1, %2, %0;" : "+l"(d) : "l"(a), "l"(w));
    return d;
}
__device__ __forceinline__ u64t mul2(u64t a, u64t b) {
    u64t r; asm("mul.rn.f32x2 %0, %1, %2;" : "=l"(r) : "l"(a), "l"(b));
    return r;
}
__device__ __forceinline__ u64t add2(u64t a, u64t b) {
    u64t r; asm("add.rn.f32x2 %0, %1, %2;" : "=l"(r) : "l"(a), "l"(b));
    return r;
}
__device__ __forceinline__ u64t neg2(u64t a) {
    return a ^ 0x8000000080000000ull;
}
// Packed reciprocal: bit-trick seed (no cross-lane borrow: both halves of
// den are positive with bits < 0x7EF311C3) + 3 Newton steps. FMA-pipe only.
__device__ __forceinline__ u64t rcp2(u64t x, u64t two2) {
    u64t r = 0x7EF311C37EF311C3ull - x;
#pragma unroll
    for (int it = 0; it < 3; it++)
        r = mul2(r, add2(two2, neg2(mul2(x, r))));
    return r;
}

// ---------------------------------------------------------------------------
// Pass A: x-conv then y-conv for one 32(x) x 80(y) tile of one z-slice.
// grid = (10 tiles, 160 z, 4 b), block = 576 threads.  (unchanged)
// ---------------------------------------------------------------------------
__global__ void __launch_bounds__(576, 1)
pass_xy(const float* __restrict__ img1, const float* __restrict__ img2) {
    extern __shared__ u64t dsm[];
    u64t* sAC = dsm;                 // (a,c) interleaved input, [90][43]
    u64t* tm  = dsm + OFF_TM;        // (m1,m2)   x-conv plane, [90][33]
    u64t* te  = dsm + OFF_TE;        // (e11,e22) x-conv plane, [90][33]
    float* ts = (float*)(dsm + OFF_TS);   // e12 x-conv plane, [90][33]

    const int tile = blockIdx.x;            // 0..9
    const int x0 = (tile % 5) * 32;
    const int y0 = (tile / 5) * 80;
    const int z  = blockIdx.y;
    const int b  = blockIdx.z;
    const int tid = threadIdx.x;

    if (tile == 0 && z == 0 && b == 0 && tid == 0) g_sum = 0.0;  // fold init

    const float* p1 = img1 + (long long)b * VOL + (long long)z * DD;
    const float* p2 = img2 + (long long)b * VOL + (long long)z * DD;

    // Stage 1: prefetch 42x90 halo region (MLP-batched), store interleaved.
    {
        float ra[7], rc[7];
#pragma unroll
        for (int it = 0; it < 7; it++) {
            const int l = tid + it * 576;
            float a = 0.f, c = 0.f;
            if (l < RYA * RXA) {
                const int j = l / RXA, i = l - j * RXA;
                const int gy = y0 - 5 + j;
                const int gx = x0 - 5 + i;
                if (gy >= 0 && gy < D && gx >= 0 && gx < D) {
                    a = p1[gy * D + gx];
                    c = p2[gy * D + gx];
                }
            }
            ra[it] = a; rc[it] = c;
        }
#pragma unroll
        for (int it = 0; it < 7; it++) {
            const int l = tid + it * 576;
            if (l < RYA * RXA)
                sAC[(l / RXA) * SXA + (l % RXA)] = pk(ra[it], rc[it]);
        }
    }
    __syncthreads();

    u64t W2[11];
#pragma unroll
    for (int k = 0; k < 11; k++) W2[k] = pk(W[k], W[k]);

    // Stage 2: x-conv, 90 rows x 8 chunks of 4 outputs = 720 units.
    for (int u = tid; u < RYA * 8; u += 576) {
        const int row   = u % RYA;
        const int chunk = u / RYA;
        const int base = row * SXA + chunk * 4;
        u64t ac[14], sq[14];
        float p12[14];
#pragma unroll
        for (int j = 0; j < 14; j++) ac[j] = sAC[base + j];
#pragma unroll
        for (int j = 0; j < 14; j++) {
            sq[j] = mul2(ac[j], ac[j]);
            const float2 t = unpk(ac[j]);
            p12[j] = t.x * t.y;
        }
#pragma unroll
        for (int i = 0; i < 4; i++) {
            u64t am = 0ull, ae = 0ull;
            float a12 = 0.f;
#pragma unroll
            for (int k = 0; k < 11; k++) {
                am  = fma2(ac[i + k], W2[k], am);
                ae  = fma2(sq[i + k], W2[k], ae);
                a12 = fmaf(W[k], p12[i + k], a12);
            }
            const int x = chunk * 4 + i;
            tm[row * TSA + x] = am;
            te[row * TSA + x] = ae;
            ts[row * TSA + x] = a12;
        }
    }
    __syncthreads();

    // Stage 3: y-conv (80 outputs in 8 chunks of 10), write fp16 planes.
    const long long cs = (long long)NB * VOL;
    for (int u = tid; u < 768; u += 576) {
        const int g = u >> 8;
        const int r = u & 255;
        const int tx = r & 31;
        const int sub = r >> 5;              // y chunk of 10
        __half* o0 = g_mid + (long long)b * VOL + (long long)z * DD + x0 + tx;

        if (g < 2) {
            const u64t* tp = (g == 0) ? tm : te;
            __half* q0 = o0 + (g == 0 ? 0 : 2 * cs);
            __half* q1 = q0 + cs;
            u64t v[20];
#pragma unroll
            for (int j = 0; j < 20; j++)
                v[j] = tp[(sub * 10 + j) * TSA + tx];
#pragma unroll
            for (int i = 0; i < 10; i++) {
                u64t acc = 0ull;
#pragma unroll
                for (int k = 0; k < 11; k++) acc = fma2(v[i + k], W2[k], acc);
                const float2 f = unpk(acc);
                const long long yo = (long long)(y0 + sub * 10 + i) * D;
                q0[yo] = __float2half_rn(f.x);
                q1[yo] = __float2half_rn(f.y);
            }
        } else {
            __half* q4 = o0 + 4 * cs;
            float v[20];
#pragma unroll
            for (int j = 0; j < 20; j++)
                v[j] = ts[(sub * 10 + j) * TSA + tx];
#pragma unroll
            for (int i = 0; i < 10; i++) {
                float acc = 0.f;
#pragma unroll
                for (int k = 0; k < 11; k++) acc = fmaf(W[k], v[i + k], acc);
                q4[(long long)(y0 + sub * 10 + i) * D] = __float2half_rn(acc);
            }
        }
    }
}

// ---------------------------------------------------------------------------
// Pass B: z-conv + packed SSIM + reduction, 32(x) x 32(z) tiles.
// grid = (25 tiles [x,z], 160 y, 4 b), block = 128 threads, >=4 blocks/SM.
// ---------------------------------------------------------------------------
__global__ void __launch_bounds__(128, 4) pass_z() {
    __shared__ u64t u5[5 * RZ * UZP];   // 28.56 kB
    __shared__ float red[4];

    const int tile = blockIdx.x;
    const int x0 = (tile % 5) * 32;
    const int z0 = (tile / 5) * 32;
    const int y  = blockIdx.y;
    const int b  = blockIdx.z;
    const int tid = threadIdx.x;

    const long long cs = (long long)NB * VOL;
    const __half* basep = g_mid + (long long)b * VOL + (long long)y * D + x0;

    // Fill: 5 channels x 42 z-rows x 4 uint4-chunks (8 halfs each).
    // All 7 loads issued before any store (MLP=7).
    {
        uint4 hv[7];
#pragma unroll
        for (int it = 0; it < 7; it++) {
            const int l = tid + it * 128;
            hv[it] = make_uint4(0u, 0u, 0u, 0u);
            if (l < 5 * RZ * 4) {
                const int ch  = l / (RZ * 4);
                const int rem = l - ch * (RZ * 4);
                const int zz  = rem >> 2;
                const int q   = rem & 3;
                const int gz  = z0 - 5 + zz;
                if (gz >= 0 && gz < D)
                    hv[it] = *(const uint4*)(basep + ch * cs +
                                             (long long)gz * DD + 8 * q);
            }
        }
#pragma unroll
        for (int it = 0; it < 7; it++) {
            const int l = tid + it * 128;
            if (l < 5 * RZ * 4) {
                const int ch  = l / (RZ * 4);
                const int rem = l - ch * (RZ * 4);
                const int zz  = rem >> 2;
                const int q   = rem & 3;
                float2 f;
                u64t* dst = &u5[(ch * RZ + zz) * UZP + 4 * q];
                f = __half22float2(*(const __half2*)&hv[it].x);
                dst[0] = pk(f.x, f.y);
                f = __half22float2(*(const __half2*)&hv[it].y);
                dst[1] = pk(f.x, f.y);
                f = __half22float2(*(const __half2*)&hv[it].z);
                dst[2] = pk(f.x, f.y);
                f = __half22float2(*(const __half2*)&hv[it].w);
                dst[3] = pk(f.x, f.y);
            }
        }
    }
    __syncthreads();

    // Symmetric weights: only W[0..5] needed (W[k] == W[10-k]).
    u64t W2[6];
#pragma unroll
    for (int k = 0; k < 6; k++) W2[k] = pk(W[k], W[k]);

    // Each thread: one x-pair, 4 z-outputs.
    const int xp = tid & 15;
    const int zc = tid >> 4;            // 0..7
    u64t rr[5][4];
#pragma unroll
    for (int ch = 0; ch < 5; ch++) {
        u64t v[14];
#pragma unroll
        for (int j = 0; j < 14; j++)
            v[j] = u5[(ch * RZ + zc * 4 + j) * UZP + xp];
#pragma unroll
        for (int i = 0; i < 4; i++) {
            u64t acc = mul2(v[i + 5], W2[5]);
#pragma unroll
            for (int k = 0; k < 5; k++)
                acc = fma2(add2(v[i + k], v[i + 10 - k]), W2[k], acc);
            rr[ch][i] = acc;
        }
    }

    // Packed SSIM map.
    const u64t two2 = pk(2.f, 2.f);
    const u64t c1p  = pk(C1, C1);
    const u64t c2p  = pk(C2, C2);
    u64t lacc = 0ull;
#pragma unroll
    for (int i = 0; i < 4; i++) {
        const u64t mu1 = rr[0][i], mu2 = rr[1][i];
        const u64t e11 = rr[2][i], e22 = rr[3][i], e12 = rr[4][i];
        const u64t mu1s = mul2(mu1, mu1);
        const u64t mu2s = mul2(mu2, mu2);
        const u64t mu12 = mul2(mu1, mu2);
        const u64t num1 = fma2(mu12, two2, c1p);
        const u64t num2 = fma2(add2(e12, neg2(mu12)), two2, c2p);
        const u64t den1 = add2(add2(mu1s, mu2s), c1p);
        const u64t den2 = add2(add2(add2(e11, neg2(mu1s)),
                                    add2(e22, neg2(mu2s))), c2p);
        lacc = fma2(mul2(num1, num2), rcp2(mul2(den1, den2), two2), lacc);
    }
    const float2 lf = unpk(lacc);
    float lsum = lf.x + lf.y;

    // Block reduction (4 warps).
#pragma unroll
    for (int o = 16; o > 0; o >>= 1)
        lsum += __shfl_xor_sync(0xffffffffu, lsum, o);
    if ((tid & 31) == 0) red[tid >> 5] = lsum;
    __syncthreads();
    if (tid == 0) {
        float s = 0.f;
#pragma unroll
        for (int w = 0; w < 4; w++) s += red[w];
        atomicAdd(&g_sum, (double)s);
    }
}

__global__ void fin_kernel(float* __restrict__ out) {
    out[0] = (float)(g_sum / (double)NIMG);
}

extern "C" void kernel_launch(void* const* d_in, const int* in_sizes, int n_in,
                              void* d_out, int out_size) {
    const float* img1 = (const float*)d_in[0];
    const float* img2 = (const float*)d_in[1];
    (void)in_sizes; (void)n_in; (void)out_size;

    cudaFuncSetAttribute(pass_xy, cudaFuncAttributeMaxDynamicSharedMemorySize,
                         SMEM_XY);

    dim3 grid(10, 160, 4);
    pass_xy<<<grid, 576, SMEM_XY>>>(img1, img2);
    dim3 gridz(25, 160, 4);
    pass_z<<<gridz, 128>>>();
    fin_kernel<<<1, 1>>>((float*)d_out);
}